// round 2
// baseline (speedup 1.0000x reference)
#include <cuda_runtime.h>
#include <cuda_bf16.h>
#include <cstdint>

#define NN 50000
#define EE 800000
#define TOT (EE + NN)

// ---------------- scratch (static device globals; no allocations) ----------------
__device__ float g_h[(size_t)NN * 128];          // per-conv GEMM output
__device__ float g_z1[2][(size_t)NN * 128];      // xZ1 (real), xfZ1 (fake)
__device__ float g_as[NN * 2];                   // alpha_src per node per head
__device__ float g_ad[NN * 2];                   // alpha_dst per node per head
__device__ int   g_counts[NN];
__device__ int   g_rowstart[2][NN + 1];
__device__ int   g_cursor[NN];
__device__ int   g_csr[2][TOT];                  // incoming-edge source lists (CSR by dst)

__device__ __forceinline__ float lrelu(float v, float s) { return v > 0.f ? v : s * v; }

// ---------------- CSR build ----------------
__global__ void fill_counts_kernel() {
    int i = blockIdx.x * blockDim.x + threadIdx.x;
    if (i < NN) g_counts[i] = 1;                 // self loop
}

__global__ void hist_kernel(const int* __restrict__ ei) {
    int i = blockIdx.x * blockDim.x + threadIdx.x;
    if (i < EE) atomicAdd(&g_counts[ei[EE + i]], 1);
}

__global__ void scan_kernel(int g) {
    __shared__ int part[1024];
    const int tid = threadIdx.x;
    const int chunk = (NN + 1023) / 1024;        // 49
    int s = tid * chunk;
    int e = s + chunk; if (e > NN) e = NN; if (s > NN) s = NN;
    int sum = 0;
    for (int i = s; i < e; i++) sum += g_counts[i];
    part[tid] = sum;
    __syncthreads();
    for (int off = 1; off < 1024; off <<= 1) {
        int v = (tid >= off) ? part[tid - off] : 0;
        __syncthreads();
        part[tid] += v;
        __syncthreads();
    }
    int base = tid ? part[tid - 1] : 0;
    for (int i = s; i < e; i++) { g_rowstart[g][i] = base; base += g_counts[i]; }
    if (tid == 1023) g_rowstart[g][NN] = part[1023];
}

__global__ void cursor_kernel(int g) {
    int i = blockIdx.x * blockDim.x + threadIdx.x;
    if (i < NN) g_cursor[i] = g_rowstart[g][i];
}

__global__ void scatter_kernel(const int* __restrict__ ei, int g) {
    int i = blockIdx.x * blockDim.x + threadIdx.x;
    if (i >= TOT) return;
    int src, dst;
    if (i < EE) { src = ei[i]; dst = ei[EE + i]; }
    else        { src = i - EE; dst = src; }
    int p = atomicAdd(&g_cursor[dst], 1);
    g_csr[g][p] = src;
}

// ---------------- GEMM: O[M,128] = X[M,128] @ W[128,128]  (64x64 tiles) ----------------
__global__ void gemm_kernel(const float* __restrict__ X, const float* __restrict__ W,
                            float* __restrict__ O) {
    __shared__ float Ws[128 * 64];
    const int t  = threadIdx.x;                  // 256 threads
    const int tx = t & 15, ty = t >> 4;
    const int row0 = blockIdx.x * 64;
    const int col0 = blockIdx.y * 64;

    {   // stage W[:, col0:col0+64] into smem
        const float4* Wsrc = (const float4*)W;   // row stride = 32 float4
        float4* Wd = (float4*)Ws;
#pragma unroll
        for (int i = 0; i < 8; i++) {
            int idx = t + i * 256;               // 0..2047
            int kr = idx >> 4;                   // k row 0..127
            int c4 = idx & 15;                   // col float4 0..15
            Wd[idx] = Wsrc[kr * 32 + (col0 >> 2) + c4];
        }
    }
    __syncthreads();

    float acc[4][4];
#pragma unroll
    for (int r = 0; r < 4; r++)
#pragma unroll
        for (int c = 0; c < 4; c++) acc[r][c] = 0.f;

    const float* xrow[4];
#pragma unroll
    for (int r = 0; r < 4; r++) {
        int row = row0 + ty * 4 + r;
        if (row >= NN) row = NN - 1;             // clamp (stores are guarded)
        xrow[r] = X + (size_t)row * 128;
    }

#pragma unroll 4
    for (int k = 0; k < 128; k += 4) {
        float xv[4][4];
#pragma unroll
        for (int r = 0; r < 4; r++) {
            float4 v = *(const float4*)(xrow[r] + k);
            xv[r][0] = v.x; xv[r][1] = v.y; xv[r][2] = v.z; xv[r][3] = v.w;
        }
#pragma unroll
        for (int kk = 0; kk < 4; kk++) {
            float4 wv = *(const float4*)&Ws[(k + kk) * 64 + tx * 4];
            float wc0 = wv.x, wc1 = wv.y, wc2 = wv.z, wc3 = wv.w;
#pragma unroll
            for (int r = 0; r < 4; r++) {
                float xr = xv[r][kk];
                acc[r][0] += xr * wc0;
                acc[r][1] += xr * wc1;
                acc[r][2] += xr * wc2;
                acc[r][3] += xr * wc3;
            }
        }
    }

#pragma unroll
    for (int r = 0; r < 4; r++) {
        int row = row0 + ty * 4 + r;
        if (row < NN) {
            float4 o = make_float4(acc[r][0], acc[r][1], acc[r][2], acc[r][3]);
            *(float4*)(O + (size_t)row * 128 + col0 + tx * 4) = o;
        }
    }
}

// ---------------- alpha_src / alpha_dst: per node per head dot products ----------------
__global__ void alpha_kernel(const float* __restrict__ H,
                             const float* __restrict__ a_src,
                             const float* __restrict__ a_dst) {
    int w = (blockIdx.x * blockDim.x + threadIdx.x) >> 5;
    if (w >= NN) return;
    int lane = threadIdx.x & 31;
    int head = lane >> 4;
    int d0 = (lane & 15) * 4;
    float4 v = *(const float4*)(H + (size_t)w * 128 + lane * 4);
    const float* as = a_src + head * 64 + d0;
    const float* ad = a_dst + head * 64 + d0;
    float s = v.x * as[0] + v.y * as[1] + v.z * as[2] + v.w * as[3];
    float d = v.x * ad[0] + v.y * ad[1] + v.z * ad[2] + v.w * ad[3];
#pragma unroll
    for (int off = 8; off >= 1; off >>= 1) {
        s += __shfl_xor_sync(0xffffffffu, s, off);
        d += __shfl_xor_sync(0xffffffffu, d, off);
    }
    if ((lane & 15) == 0) {
        g_as[w * 2 + head] = s;
        g_ad[w * 2 + head] = d;
    }
}

// ---------------- softmax aggregation: one warp per destination node ----------------
__global__ void agg_kernel(const float* __restrict__ H, int g,
                           const float* __restrict__ bias,
                           float* __restrict__ out, int do_relu) {
    int w = (blockIdx.x * blockDim.x + threadIdx.x) >> 5;
    if (w >= NN) return;
    int lane = threadIdx.x & 31;
    int beg = g_rowstart[g][w], end = g_rowstart[g][w + 1];
    float ad0 = g_ad[w * 2], ad1 = g_ad[w * 2 + 1];

    // online softmax stats (m, s) per head
    float m0 = -1e30f, m1 = -1e30f, s0 = 0.f, s1 = 0.f;
    for (int e = beg + lane; e < end; e += 32) {
        int src = g_csr[g][e];
        float2 av = *(const float2*)&g_as[src * 2];
        float e0 = lrelu(av.x + ad0, 0.2f);
        float e1 = lrelu(av.y + ad1, 0.2f);
        if (e0 > m0) { s0 = s0 * __expf(m0 - e0) + 1.f; m0 = e0; } else s0 += __expf(e0 - m0);
        if (e1 > m1) { s1 = s1 * __expf(m1 - e1) + 1.f; m1 = e1; } else s1 += __expf(e1 - m1);
    }
#pragma unroll
    for (int off = 16; off >= 1; off >>= 1) {
        float mo = __shfl_xor_sync(0xffffffffu, m0, off);
        float so = __shfl_xor_sync(0xffffffffu, s0, off);
        float mn = fmaxf(m0, mo);
        s0 = s0 * __expf(m0 - mn) + so * __expf(mo - mn); m0 = mn;
        mo = __shfl_xor_sync(0xffffffffu, m1, off);
        so = __shfl_xor_sync(0xffffffffu, s1, off);
        mn = fmaxf(m1, mo);
        s1 = s1 * __expf(m1 - mn) + so * __expf(mo - mn); m1 = mn;
    }
    float inv0 = 1.f / s0;
    float inv1 = 1.f / s1;

    const int col  = lane * 4;
    const int head = lane >> 4;
    float4 acc = make_float4(0.f, 0.f, 0.f, 0.f);

    for (int base = beg; base < end; base += 32) {
        int cnt = end - base; if (cnt > 32) cnt = 32;
        int   sidx = 0; float aa0 = 0.f, aa1 = 0.f;
        if (lane < cnt) {
            sidx = g_csr[g][base + lane];
            float2 av = *(const float2*)&g_as[sidx * 2];
            float e0 = lrelu(av.x + ad0, 0.2f);
            float e1 = lrelu(av.y + ad1, 0.2f);
            aa0 = __expf(e0 - m0) * inv0;
            aa1 = __expf(e1 - m1) * inv1;
        }
        for (int j = 0; j < cnt; j++) {
            int   sj  = __shfl_sync(0xffffffffu, sidx, j);
            float a0j = __shfl_sync(0xffffffffu, aa0, j);
            float a1j = __shfl_sync(0xffffffffu, aa1, j);
            float aj  = head ? a1j : a0j;
            float4 v = *(const float4*)(H + (size_t)sj * 128 + col);
            acc.x += aj * v.x; acc.y += aj * v.y; acc.z += aj * v.z; acc.w += aj * v.w;
        }
    }

    float4 bv = *(const float4*)(bias + col);
    float4 r = make_float4(acc.x + bv.x, acc.y + bv.y, acc.z + bv.z, acc.w + bv.w);
    if (do_relu) {
        r.x = fmaxf(r.x, 0.f); r.y = fmaxf(r.y, 0.f);
        r.z = fmaxf(r.z, 0.f); r.w = fmaxf(r.w, 0.f);
    }
    *(float4*)(out + (size_t)w * 128 + col) = r;
}

// ---------------- tprob = leaky_relu(xZ2 @ Wp + bp, 0.01) ----------------
__global__ void tprob_kernel(const float* __restrict__ Z, const float* __restrict__ Wp,
                             const float* __restrict__ bp, float* __restrict__ out) {
    int w = (blockIdx.x * blockDim.x + threadIdx.x) >> 5;
    if (w >= NN) return;
    int lane = threadIdx.x & 31;
    int col = lane * 4;
    float4 v  = *(const float4*)(Z + (size_t)w * 128 + col);
    float4 p0 = *(const float4*)(Wp + col * 2);
    float4 p1 = *(const float4*)(Wp + col * 2 + 4);
    float a0 = v.x * p0.x + v.y * p0.z + v.z * p1.x + v.w * p1.z;
    float a1 = v.x * p0.y + v.y * p0.w + v.z * p1.y + v.w * p1.w;
#pragma unroll
    for (int off = 16; off >= 1; off >>= 1) {
        a0 += __shfl_xor_sync(0xffffffffu, a0, off);
        a1 += __shfl_xor_sync(0xffffffffu, a1, off);
    }
    if (lane == 0) {
        float o0 = lrelu(a0 + bp[0], 0.01f);
        float o1 = lrelu(a1 + bp[1], 0.01f);
        *(float2*)(out + (size_t)w * 2) = make_float2(o0, o1);
    }
}

// ---------------- y heads: lrelu(lrelu(Z[idx]@WyS+byS,.01)@Wy+by,.01) ----------------
__global__ void head_kernel(const float* __restrict__ Z, const int* __restrict__ idx,
                            const float* __restrict__ WyS, const float* __restrict__ byS,
                            const float* __restrict__ Wy, const float* __restrict__ by,
                            float* __restrict__ yout, int cnt) {
    int i = blockIdx.x;
    if (i >= cnt) return;
    int t = threadIdx.x;                         // 64
    __shared__ float zs[128];
    __shared__ float red[2];
    int node = idx[i];
    const float* z = Z + (size_t)node * 128;
    zs[t] = z[t]; zs[t + 64] = z[t + 64];
    __syncthreads();
    float acc = byS[t];
#pragma unroll 8
    for (int k = 0; k < 128; k++) acc += zs[k] * WyS[k * 64 + t];
    acc = lrelu(acc, 0.01f);
    float p = acc * Wy[t];
#pragma unroll
    for (int off = 16; off >= 1; off >>= 1) p += __shfl_xor_sync(0xffffffffu, p, off);
    if ((t & 31) == 0) red[t >> 5] = p;
    __syncthreads();
    if (t == 0) {
        float s = red[0] + red[1] + by[0];
        yout[i] = lrelu(s, 0.01f);
    }
}

// ---------------- launch ----------------
static void build_csr(const int* ei, int g) {
    fill_counts_kernel<<<(NN + 255) / 256, 256>>>();
    hist_kernel<<<(EE + 255) / 256, 256>>>(ei);
    scan_kernel<<<1, 1024>>>(g);
    cursor_kernel<<<(NN + 255) / 256, 256>>>(g);
    scatter_kernel<<<(TOT + 255) / 256, 256>>>(ei, g);
}

static void run_conv(const float* Xin, const float* W, const float* asrc, const float* adst,
                     const float* bias, int g, float* outp, int do_relu, float* hbuf) {
    gemm_kernel<<<dim3((NN + 63) / 64, 2), 256>>>(Xin, W, hbuf);
    alpha_kernel<<<(NN * 32) / 256, 256>>>(hbuf, asrc, adst);
    agg_kernel<<<(NN * 32) / 256, 256>>>(hbuf, g, bias, outp, do_relu);
}

extern "C" void kernel_launch(void* const* d_in, const int* in_sizes, int n_in,
                              void* d_out, int out_size) {
    const float* x       = (const float*)d_in[0];
    const int*   ei      = (const int*)d_in[1];
    const float* fx      = (const float*)d_in[2];
    const int*   fei     = (const int*)d_in[3];
    const int*   treat   = (const int*)d_in[4];
    const int*   control = (const int*)d_in[5];
    const float* W1      = (const float*)d_in[6];
    const float* as1     = (const float*)d_in[7];
    const float* ad1     = (const float*)d_in[8];
    const float* b1      = (const float*)d_in[9];
    const float* W2      = (const float*)d_in[10];
    const float* as2     = (const float*)d_in[11];
    const float* ad2     = (const float*)d_in[12];
    const float* b2      = (const float*)d_in[13];
    const float* WyS     = (const float*)d_in[14];
    const float* byS     = (const float*)d_in[15];
    const float* Wy1     = (const float*)d_in[16];
    const float* by1     = (const float*)d_in[17];
    const float* Wy0     = (const float*)d_in[18];
    const float* by0     = (const float*)d_in[19];
    const float* Wp      = (const float*)d_in[20];
    const float* bp      = (const float*)d_in[21];
    float* out = (float*)d_out;
    const int nt = in_sizes[4];
    const int nc = in_sizes[5];

    float* hbuf = nullptr;
    float* z1   = nullptr;
    cudaGetSymbolAddress((void**)&hbuf, g_h);
    cudaGetSymbolAddress((void**)&z1, g_z1);
    float* z1a = z1;
    float* z1b = z1 + (size_t)NN * 128;

    const size_t OFF_Y1   = 0;
    const size_t OFF_YC0  = 5000;
    const size_t OFF_Y0   = 10000;
    const size_t OFF_YC1  = 15000;
    const size_t OFF_XZ2  = 20000;
    const size_t OFF_XFZ2 = OFF_XZ2 + (size_t)NN * 128;
    const size_t OFF_TP   = OFF_XFZ2 + (size_t)NN * 128;

    build_csr(ei, 0);
    build_csr(fei, 1);

    run_conv(x,   W1, as1, ad1, b1, 0, z1a, 1, hbuf);
    run_conv(fx,  W1, as1, ad1, b1, 1, z1b, 1, hbuf);
    run_conv(z1a, W2, as2, ad2, b2, 0, out + OFF_XZ2,  0, hbuf);
    run_conv(z1b, W2, as2, ad2, b2, 1, out + OFF_XFZ2, 0, hbuf);

    tprob_kernel<<<(NN * 32) / 256, 256>>>(out + OFF_XZ2, Wp, bp, out + OFF_TP);

    head_kernel<<<nt, 64>>>(out + OFF_XZ2,  treat,   WyS, byS, Wy1, by1, out + OFF_Y1,  nt);
    head_kernel<<<nt, 64>>>(out + OFF_XFZ2, treat,   WyS, byS, Wy0, by0, out + OFF_YC0, nt);
    head_kernel<<<nc, 64>>>(out + OFF_XZ2,  control, WyS, byS, Wy0, by0, out + OFF_Y0,  nc);
    head_kernel<<<nc, 64>>>(out + OFF_XFZ2, control, WyS, byS, Wy1, by1, out + OFF_YC1, nc);
}